// round 3
// baseline (speedup 1.0000x reference)
#include <cuda_runtime.h>

// CNODExtmod: controlled neural ODE, persistent per-CTA time loop.
// BATCH=4096 rows, T=64 obs steps x 4 Euler substeps.
// State h = [cn0 (32) | cn1 (33)]; per substep:
//   dcn0 = A @ cn0 + Bvec * cn1[0]
//   dcn1 = W3 @ relu(W2 @ relu(W1 @ cn1 + b1) + b2) + b3
//   h += 0.01 * [dcn0, dcn1]
// Obs: y_pred = cn1[0]; if mask: cn1 = [y_t, cn0].

#define NCC      32
#define NC1      33
#define HID      128
#define TT       64
#define NSUB     4
#define ROWS     32      // batch rows per CTA
#define NTHREADS 256
#define DTC      0.01f
#define CNS      36      // padded row stride for cn0/cn1 (16B aligned)
#define XS       128     // row stride for X1/X2

#define O_Y2 262144      // second y_preds copy
#define O_T  524288      // times
#define O_H  524352      // final cn0

// NOTE: parameter names must not collide with float4 members (.x/.y/.z/.w)
#define FMA4(acc, xv, wt, bofs) {                        \
    acc = fmaf((wt)[(bofs)+0], (xv).x, acc);             \
    acc = fmaf((wt)[(bofs)+1], (xv).y, acc);             \
    acc = fmaf((wt)[(bofs)+2], (xv).z, acc);             \
    acc = fmaf((wt)[(bofs)+3], (xv).w, acc); }

__global__ void __launch_bounds__(NTHREADS, 1)
cnode_kernel(const float* __restrict__ times, const float* __restrict__ Y,
             const float* __restrict__ mask,  const float* __restrict__ A,
             const float* __restrict__ Bvec,
             const float* __restrict__ W1, const float* __restrict__ b1,
             const float* __restrict__ W2, const float* __restrict__ b2,
             const float* __restrict__ W3, const float* __restrict__ b3,
             float* __restrict__ out)
{
    __shared__ __align__(16) float CN0[ROWS * CNS];
    __shared__ __align__(16) float CN1[ROWS * CNS];
    __shared__ __align__(16) float X1 [ROWS * XS];
    __shared__ __align__(16) float X2 [ROWS * XS];
    __shared__ __align__(16) float DC1[ROWS * NCC];
    __shared__ float ysh[ROWS];
    __shared__ float msh[ROWS];

    const int tid = threadIdx.x;
    const int b0  = blockIdx.x * ROWS;

    // role decompositions
    const int j  = tid >> 1;   // 0..127 : output col for L1/L2
    const int s  = tid & 1;    // K-half for L1/L2
    const int j3 = tid >> 3;   // 0..31  : output col for L3 / row for out32 col
    const int s3 = tid & 7;    // K-eighth for L3/out32
    const int ia = tid & 31;   // 0..31  : output col for A pass
    const int rg = tid >> 5;   // warp id : row group for A pass

    // ---- load weights into registers (once) ----
    float w1r[17];
    #pragma unroll
    for (int i = 0; i < 16; i++) w1r[i] = W1[j * NC1 + s * 16 + i];
    w1r[16] = s ? W1[j * NC1 + 32] : 0.0f;   // s=0 slice is k0..15 only
    const float b1j = b1[j];

    float w2r[64];
    #pragma unroll
    for (int i = 0; i < 64; i++) w2r[i] = W2[j * HID + s * 64 + i];
    const float b2j = b2[j];

    // L3 K-slicing: thread s3 owns k = s3*4 + 32*m + q (m<4, q<4).
    // The 8 slices' 16B lines land on distinct banks -> conflict-free LDS.128.
    float w3r[16];
    #pragma unroll
    for (int m = 0; m < 4; m++)
        #pragma unroll
        for (int q = 0; q < 4; q++)
            w3r[m * 4 + q] = W3[j3 * HID + s3 * 4 + m * 32 + q];
    const float b3j = b3[j3];

    float w32r[16];   // W3 row 32 (the 33rd output), same slicing
    #pragma unroll
    for (int m = 0; m < 4; m++)
        #pragma unroll
        for (int q = 0; q < 4; q++)
            w32r[m * 4 + q] = W3[NCC * HID + s3 * 4 + m * 32 + q];
    const float b3_32 = b3[NCC];

    float wAr[32];
    #pragma unroll
    for (int k = 0; k < 32; k++) wAr[k] = A[ia * NCC + k];
    const float Bi = Bvec[ia];

    // ---- init state, times, obs prefetch ----
    for (int idx = tid; idx < ROWS * CNS; idx += NTHREADS) {
        CN0[idx] = 0.0f; CN1[idx] = 0.0f;
    }
    if (blockIdx.x == 0 && tid < TT) out[O_T + tid] = times[tid];

    float y_t = 0.0f, m_t = 0.0f;
    if (tid < ROWS) {
        y_t = Y[(b0 + tid) * TT];
        m_t = mask[(b0 + tid) * TT];
    }
    __syncthreads();

    for (int t = 0; t < TT; t++) {
        for (int sub = 0; sub < NSUB; sub++) {
            // ---------- L1: X1 = relu(W1 @ cn1 + b1) ----------
            #pragma unroll 2
            for (int r = 0; r < ROWS; r++) {
                const float* cr = CN1 + r * CNS + s * 16;
                float acc = 0.0f;
                float4 xv;
                xv = *(const float4*)(cr + 0);  FMA4(acc, xv, w1r, 0);
                xv = *(const float4*)(cr + 4);  FMA4(acc, xv, w1r, 4);
                xv = *(const float4*)(cr + 8);  FMA4(acc, xv, w1r, 8);
                xv = *(const float4*)(cr + 12); FMA4(acc, xv, w1r, 12);
                acc = fmaf(w1r[16], CN1[r * CNS + 32], acc);
                float tot = acc + __shfl_xor_sync(0xffffffffu, acc, 1);
                tot = fmaxf(tot + b1j, 0.0f);
                if (!s) X1[r * XS + j] = tot;
            }
            __syncthreads();

            // ---------- L2: X2 = relu(W2 @ X1 + b2) ----------
            #pragma unroll 2
            for (int r = 0; r < ROWS; r++) {
                const float* xr = X1 + r * XS + s * 64;
                float acc = 0.0f;
                #pragma unroll
                for (int v = 0; v < 16; v++) {
                    float4 xv = *(const float4*)(xr + v * 4);
                    FMA4(acc, xv, w2r, v * 4);
                }
                float tot = acc + __shfl_xor_sync(0xffffffffu, acc, 1);
                tot = fmaxf(tot + b2j, 0.0f);
                if (!s) X2[r * XS + j] = tot;
            }
            __syncthreads();

            // ---------- phase 3: all derivative reads, no state writes ----------
            // A pass: dcn0[i] = sum_k A[i,k]*cn0[k] + Bvec[i]*cn1[0]
            float dcn0[4];
            #pragma unroll
            for (int q = 0; q < 4; q++) {
                const int r = rg * 4 + q;
                const float* cr = CN0 + r * CNS;
                float acc = 0.0f;
                #pragma unroll
                for (int v = 0; v < 8; v++) {
                    float4 xv = *(const float4*)(cr + v * 4);
                    FMA4(acc, xv, wAr, v * 4);
                }
                dcn0[q] = fmaf(Bi, CN1[r * CNS], acc);
            }

            // out32: dcn1[32] for row j3
            float o32;
            {
                const float* xr = X2 + j3 * XS;
                float acc = 0.0f;
                #pragma unroll
                for (int m = 0; m < 4; m++) {
                    float4 xv = *(const float4*)(xr + s3 * 4 + m * 32);
                    FMA4(acc, xv, w32r, m * 4);
                }
                acc += __shfl_xor_sync(0xffffffffu, acc, 1);
                acc += __shfl_xor_sync(0xffffffffu, acc, 2);
                acc += __shfl_xor_sync(0xffffffffu, acc, 4);
                o32 = acc + b3_32;
            }

            // L3: dcn1[j3] for all rows -> DC1
            #pragma unroll 2
            for (int r = 0; r < ROWS; r++) {
                const float* xr = X2 + r * XS;
                float acc = 0.0f;
                #pragma unroll
                for (int m = 0; m < 4; m++) {
                    float4 xv = *(const float4*)(xr + s3 * 4 + m * 32);
                    FMA4(acc, xv, w3r, m * 4);
                }
                acc += __shfl_xor_sync(0xffffffffu, acc, 1);
                acc += __shfl_xor_sync(0xffffffffu, acc, 2);
                acc += __shfl_xor_sync(0xffffffffu, acc, 4);
                if (s3 == 0) DC1[r * NCC + j3] = acc + b3j;
            }
            __syncthreads();

            // ---------- phase 4: apply Euler update ----------
            #pragma unroll
            for (int q = 0; q < 4; q++) {
                const int r = rg * 4 + q;
                CN0[r * CNS + ia] += DTC * dcn0[q];
            }
            #pragma unroll
            for (int u = 0; u < 4; u++) {
                const int idx = tid + u * NTHREADS;   // 0..1023 = r*32 + jj
                const int r = idx >> 5, jj = idx & 31;
                CN1[r * CNS + jj] += DTC * DC1[idx];
            }
            if (s3 == 0) CN1[j3 * CNS + 32] += DTC * o32;
            __syncthreads();
        }

        // ---------- observation step ----------
        if (tid < ROWS) {
            const float yp = CN1[tid * CNS];
            out[(b0 + tid) * TT + t]        = yp;
            out[O_Y2 + (b0 + tid) * TT + t] = yp;
            ysh[tid] = y_t;
            msh[tid] = m_t;
        }
        __syncthreads();

        // masked update: cn1 <- [y_t, cn0] where mask==1
        for (int idx = tid; idx < ROWS * NC1; idx += NTHREADS) {
            const int r  = idx / NC1;
            const int jj = idx - r * NC1;
            if (msh[r] != 0.0f) {
                CN1[r * CNS + jj] = (jj == 0) ? ysh[r] : CN0[r * CNS + jj - 1];
            }
        }
        // prefetch next obs into registers (latency hidden behind 4 substeps)
        if (tid < ROWS && t + 1 < TT) {
            y_t = Y[(b0 + tid) * TT + t + 1];
            m_t = mask[(b0 + tid) * TT + t + 1];
        }
        __syncthreads();
    }

    // final hidden state cn0
    for (int idx = tid; idx < ROWS * NCC; idx += NTHREADS) {
        const int r = idx >> 5, i = idx & 31;
        out[O_H + (b0 + r) * NCC + i] = CN0[r * CNS + i];
    }
}

extern "C" void kernel_launch(void* const* d_in, const int* in_sizes, int n_in,
                              void* d_out, int out_size)
{
    const float* times = (const float*)d_in[0];
    const float* Y     = (const float*)d_in[1];
    const float* mask  = (const float*)d_in[2];
    const float* A     = (const float*)d_in[3];
    const float* Bvec  = (const float*)d_in[4];
    const float* W1    = (const float*)d_in[5];
    const float* b1    = (const float*)d_in[6];
    const float* W2    = (const float*)d_in[7];
    const float* b2    = (const float*)d_in[8];
    const float* W3    = (const float*)d_in[9];
    const float* b3    = (const float*)d_in[10];
    float* out = (float*)d_out;

    cnode_kernel<<<128, NTHREADS>>>(times, Y, mask, A, Bvec,
                                    W1, b1, W2, b2, W3, b3, out);
}